// round 15
// baseline (speedup 1.0000x reference)
#include <cuda_runtime.h>
#include <cuda_fp16.h>
#include <math.h>
#include <stdint.h>

#define NN 10000
#define EE 160000
#define FIN 70
#define KP 80            // FIN padded to multiple of 16
#define HHID 256
#define D1 1024          // HEADS*HID

typedef unsigned long long u64;

__device__ __forceinline__ uint32_t smem_u32(const void* p) {
    uint32_t a;
    asm("{ .reg .u64 t; cvta.to.shared.u64 t, %1; cvt.u32.u64 %0, t; }" : "=r"(a) : "l"(p));
    return a;
}
__device__ __forceinline__ float4 h4_to_f4(u64 v) {
    __half2 lo = reinterpret_cast<__half2*>(&v)[0];
    __half2 hi = reinterpret_cast<__half2*>(&v)[1];
    float2 a = __half22float2(lo), b = __half22float2(hi);
    return make_float4(a.x, a.y, b.x, b.y);
}

// ---------------- device scratch (no allocations allowed) ----------------
__device__ __align__(16) __half g_h1h[NN * D1];   // layer-1 linear out (fp16)
__device__ __align__(16) __half g_x1h[NN * D1];   // relu(agg1+b1) fp16 (GEMM2 A)
__device__ __align__(16) __half g_w1h[D1 * KP];   // W1^T fp16 [n][k], k padded to 80
__device__ __align__(16) __half g_w2h[HHID * D1]; // W2^T fp16 [n][k]
__device__ __align__(16) float g_as1[NN * 4];
__device__ __align__(16) float g_ad1[NN * 4];
__device__ __align__(16) float g_h2[NN * HHID];   // layer-2 linear out (fp32)
__device__ float g_as2[NN];
__device__ float g_ad2[NN];
__device__ __align__(16) float g_ex1s[EE * 4];    // exp(leaky) per edge, DST-SORTED
__device__ float g_ex2s[EE];
__device__ __align__(16) float g_exself1[NN * 4];
__device__ __align__(16) float g_den1[NN * 4];
__device__ float g_exself2[NN];
__device__ float g_den2[NN];
__device__ float g_pooled[HHID];
__device__ int   g_deg[NN];
__device__ int   g_offs[NN + 1];
__device__ int   g_cursor[NN];
__device__ int   g_srcs[EE];
__device__ int   g_pos[EE];      // original edge -> sorted slot

// ---------------- small utils ----------------
__global__ void k_zero() {
    int i = blockIdx.x * blockDim.x + threadIdx.x;
    if (i < NN * 4) { g_as1[i] = 0.f; g_ad1[i] = 0.f; }
    if (i < NN) { g_deg[i] = 0; g_as2[i] = 0.f; g_ad2[i] = 0.f; }
    if (i < HHID) g_pooled[i] = 0.f;
}

__global__ void k_hist(const int* __restrict__ ei) {
    int i = blockIdx.x * blockDim.x + threadIdx.x;
    if (i < EE) atomicAdd(&g_deg[ei[EE + i]], 1);
}

__global__ void k_scan() {
    __shared__ int sbuf[1024];
    int t = threadIdx.x;
    int base = t * 10;
    int loc[10];
    int sum = 0;
#pragma unroll
    for (int q = 0; q < 10; q++) {
        int idx = base + q;
        int v = (idx < NN) ? g_deg[idx] : 0;
        loc[q] = sum; sum += v;
    }
    sbuf[t] = sum;
    __syncthreads();
    for (int off = 1; off < 1024; off <<= 1) {
        int tmp = (t >= off) ? sbuf[t - off] : 0;
        __syncthreads();
        sbuf[t] += tmp;
        __syncthreads();
    }
    int excl = sbuf[t] - sum;
#pragma unroll
    for (int q = 0; q < 10; q++) {
        int idx = base + q;
        if (idx < NN) { int o = excl + loc[q]; g_offs[idx] = o; g_cursor[idx] = o; }
    }
    if (t == 1023) g_offs[NN] = sbuf[1023];
}

__global__ void k_scatter(const int* __restrict__ ei) {
    int i = blockIdx.x * blockDim.x + threadIdx.x;
    if (i < EE) {
        int dnode = ei[EE + i];
        int pos = atomicAdd(&g_cursor[dnode], 1);
        g_srcs[pos] = ei[i];
        g_pos[i] = pos;
    }
}

// ---------------- W1 [70,1024] fp32 -> g_w1h [1024][80] fp16 ------------
__global__ void k_prepW1(const float* __restrict__ W1) {
    int id = blockIdx.x * blockDim.x + threadIdx.x;  // k-major over [KP][D1]
    if (id >= KP * D1) return;
    int k = id >> 10, n = id & 1023;
    float v = (k < FIN) ? W1[k * D1 + n] : 0.f;
    g_w1h[(size_t)n * KP + k] = __float2half(v);
}

// ---------------- W2 [1024,256] fp32 -> g_w2h [256][1024] fp16 ----------
__global__ void k_prepW2(const float* __restrict__ W2) {
    __shared__ float t[32][33];
    int k0 = blockIdx.x * 32, n0 = blockIdx.y * 32;
    int tx = threadIdx.x & 31, ty = threadIdx.x >> 5;   // 256 threads
#pragma unroll
    for (int i = 0; i < 4; i++)
        t[ty + 8 * i][tx] = W2[(k0 + ty + 8 * i) * HHID + n0 + tx];
    __syncthreads();
#pragma unroll
    for (int i = 0; i < 4; i++)
        g_w2h[(size_t)(n0 + ty + 8 * i) * D1 + k0 + tx] = __float2half(t[tx][ty + 8 * i]);
}

// ---------------- GEMM1 via HMMA + fused att1 logit partials ------------
#define G1_LDS 88
__global__ void __launch_bounds__(256) k_gemm1(const float* __restrict__ x,
                                               const float* __restrict__ as,
                                               const float* __restrict__ adv) {
    __shared__ __align__(16) __half As[128][G1_LDS];
    __shared__ __align__(16) __half Bs[128][G1_LDS];
    int tid = threadIdx.x, lane = tid & 31, w = tid >> 5;
    int wm = w >> 2, wn = w & 3;
    int row0 = blockIdx.x * 128;
    int col0 = blockIdx.y * 128;

    for (int idx = tid; idx < 128 * KP; idx += 256) {
        int r = idx / KP, c = idx - r * KP;
        float v = 0.f;
        if (c < FIN && row0 + r < NN) v = x[(size_t)(row0 + r) * FIN + c];
        As[r][c] = __float2half(v);
    }
    for (int idx = tid; idx < 128 * 10; idx += 256) {
        int r = idx / 10, q = idx - r * 10;
        *reinterpret_cast<uint4*>(&Bs[r][q * 8]) =
            *reinterpret_cast<const uint4*>(&g_w1h[(size_t)(col0 + r) * KP + q * 8]);
    }
    __syncthreads();

    float acc[4][4][4];
#pragma unroll
    for (int i = 0; i < 4; i++)
#pragma unroll
        for (int j = 0; j < 4; j++)
#pragma unroll
            for (int q = 0; q < 4; q++) acc[i][j][q] = 0.f;

#pragma unroll
    for (int kh = 0; kh < 5; kh++) {
        uint32_t af[4][4], bf[4][2];
#pragma unroll
        for (int mt = 0; mt < 4; mt++) {
            int r = wm * 64 + mt * 16 + (lane & 15);
            int c = kh * 16 + (lane >> 4) * 8;
            uint32_t a = smem_u32(&As[r][c]);
            asm volatile("ldmatrix.sync.aligned.m8n8.x4.shared.b16 {%0,%1,%2,%3}, [%4];"
                : "=r"(af[mt][0]), "=r"(af[mt][1]), "=r"(af[mt][2]), "=r"(af[mt][3]) : "r"(a));
        }
#pragma unroll
        for (int nt = 0; nt < 4; nt++) {
            int r = wn * 32 + nt * 8 + (lane & 7);
            int c = kh * 16 + ((lane >> 3) & 1) * 8;
            uint32_t a = smem_u32(&Bs[r][c]);
            asm volatile("ldmatrix.sync.aligned.m8n8.x2.shared.b16 {%0,%1}, [%2];"
                : "=r"(bf[nt][0]), "=r"(bf[nt][1]) : "r"(a));
        }
#pragma unroll
        for (int mt = 0; mt < 4; mt++)
#pragma unroll
            for (int nt = 0; nt < 4; nt++)
                asm volatile(
                    "mma.sync.aligned.m16n8k16.row.col.f32.f16.f16.f32 "
                    "{%0,%1,%2,%3},{%4,%5,%6,%7},{%8,%9},{%0,%1,%2,%3};"
                    : "+f"(acc[mt][nt][0]), "+f"(acc[mt][nt][1]),
                      "+f"(acc[mt][nt][2]), "+f"(acc[mt][nt][3])
                    : "r"(af[mt][0]), "r"(af[mt][1]), "r"(af[mt][2]), "r"(af[mt][3]),
                      "r"(bf[nt][0]), "r"(bf[nt][1]));
    }

    // store h1 (fp16)
#pragma unroll
    for (int mt = 0; mt < 4; mt++) {
        int rr = row0 + wm * 64 + mt * 16 + (lane >> 2);
#pragma unroll
        for (int nt = 0; nt < 4; nt++) {
            int cc = col0 + wn * 32 + nt * 8 + 2 * (lane & 3);
            if (rr < NN)
                *reinterpret_cast<__half2*>(&g_h1h[(size_t)rr * D1 + cc]) =
                    __floats2half2_rn(acc[mt][nt][0], acc[mt][nt][1]);
            if (rr + 8 < NN)
                *reinterpret_cast<__half2*>(&g_h1h[(size_t)(rr + 8) * D1 + cc]) =
                    __floats2half2_rn(acc[mt][nt][2], acc[mt][nt][3]);
        }
    }

    // fused attention-logit partials (fp32 acc): head hd = col0>>8
    int hd = col0 >> 8;
    float2 av[4], dv[4];
#pragma unroll
    for (int nt = 0; nt < 4; nt++) {
        int cc = col0 + wn * 32 + nt * 8 + 2 * (lane & 3);
        av[nt] = *reinterpret_cast<const float2*>(&as[cc]);
        dv[nt] = *reinterpret_cast<const float2*>(&adv[cc]);
    }
#pragma unroll
    for (int mt = 0; mt < 4; mt++) {
        int r0 = row0 + wm * 64 + mt * 16 + (lane >> 2);
        float ps0 = 0.f, pd0 = 0.f, ps1 = 0.f, pd1 = 0.f;
#pragma unroll
        for (int nt = 0; nt < 4; nt++) {
            ps0 += acc[mt][nt][0] * av[nt].x + acc[mt][nt][1] * av[nt].y;
            pd0 += acc[mt][nt][0] * dv[nt].x + acc[mt][nt][1] * dv[nt].y;
            ps1 += acc[mt][nt][2] * av[nt].x + acc[mt][nt][3] * av[nt].y;
            pd1 += acc[mt][nt][2] * dv[nt].x + acc[mt][nt][3] * dv[nt].y;
        }
#pragma unroll
        for (int o = 1; o <= 2; o <<= 1) {
            ps0 += __shfl_xor_sync(0xffffffffu, ps0, o);
            pd0 += __shfl_xor_sync(0xffffffffu, pd0, o);
            ps1 += __shfl_xor_sync(0xffffffffu, ps1, o);
            pd1 += __shfl_xor_sync(0xffffffffu, pd1, o);
        }
        if ((lane & 3) == 0) {
            if (r0 < NN) {
                atomicAdd(&g_as1[r0 * 4 + hd], ps0);
                atomicAdd(&g_ad1[r0 * 4 + hd], pd0);
            }
            if (r0 + 8 < NN) {
                atomicAdd(&g_as1[(r0 + 8) * 4 + hd], ps1);
                atomicAdd(&g_ad1[(r0 + 8) * 4 + hd], pd1);
            }
        }
    }
}

// ---------------- self-loop ex + den init, layer 1 ----------------------
__global__ void k_self1() {
    int i = blockIdx.x * blockDim.x + threadIdx.x;
    if (i >= NN * 4) return;
    float e = g_as1[i] + g_ad1[i];
    e = e > 0.f ? e : 0.2f * e;
    float ex = expf(e);
    g_exself1[i] = ex;
    g_den1[i] = ex;
}

// ---------------- edge kernel layer 1: ex (sorted) + denom atomics -----
__global__ void k_edge1(const int* __restrict__ ei) {
    int i = blockIdx.x * blockDim.x + threadIdx.x;
    if (i >= EE) return;
    int s = ei[i], d = ei[EE + i];
    float4 a = *reinterpret_cast<const float4*>(&g_as1[s * 4]);
    float4 b = *reinterpret_cast<const float4*>(&g_ad1[d * 4]);
    float e0 = a.x + b.x; e0 = e0 > 0.f ? e0 : 0.2f * e0; e0 = expf(e0);
    float e1 = a.y + b.y; e1 = e1 > 0.f ? e1 : 0.2f * e1; e1 = expf(e1);
    float e2 = a.z + b.z; e2 = e2 > 0.f ? e2 : 0.2f * e2; e2 = expf(e2);
    float e3 = a.w + b.w; e3 = e3 > 0.f ? e3 : 0.2f * e3; e3 = expf(e3);
    int pos = g_pos[i];
    *reinterpret_cast<float4*>(&g_ex1s[(size_t)pos * 4]) = make_float4(e0, e1, e2, e3);
    atomicAdd(&g_den1[d * 4 + 0], e0);
    atomicAdd(&g_den1[d * 4 + 1], e1);
    atomicAdd(&g_den1[d * 4 + 2], e2);
    atomicAdd(&g_den1[d * 4 + 3], e3);
}

// ---------------- layer-1 aggregation: single pass, vectorized ---------
// thread t handles channels [4t, 4t+4) -> one head per thread (h = t>>6)
__global__ void k_agg1(const float* __restrict__ b1) {
    int d = blockIdx.x, t = threadIdx.x;
    int beg = g_offs[d], cnt = g_offs[d + 1] - beg;
    int h = t >> 6;
    const u64* hb = reinterpret_cast<const u64*>(g_h1h);

    // self-loop term
    float ex = g_exself1[d * 4 + h];
    float4 f = h4_to_f4(hb[(size_t)d * 256 + t]);
    float ax = ex * f.x, ay = ex * f.y, az = ex * f.z, aw = ex * f.w;

#pragma unroll 4
    for (int i = 0; i < cnt; i++) {
        int s = g_srcs[beg + i];
        float e = g_ex1s[(size_t)(beg + i) * 4 + h];
        float4 g = h4_to_f4(hb[(size_t)s * 256 + t]);
        ax += e * g.x; ay += e * g.y; az += e * g.z; aw += e * g.w;
    }

    float inv = 1.f / (g_den1[d * 4 + h] + 1e-16f);
    float4 bb = *reinterpret_cast<const float4*>(&b1[4 * t]);
    __half2 lo = __floats2half2_rn(fmaxf(ax * inv + bb.x, 0.f),
                                   fmaxf(ay * inv + bb.y, 0.f));
    __half2 hi = __floats2half2_rn(fmaxf(az * inv + bb.z, 0.f),
                                   fmaxf(aw * inv + bb.w, 0.f));
    u64 outv;
    reinterpret_cast<__half2*>(&outv)[0] = lo;
    reinterpret_cast<__half2*>(&outv)[1] = hi;
    *reinterpret_cast<u64*>(&g_x1h[(size_t)d * D1 + 4 * t]) = outv;
}

// ---------------- GEMM2 via mma.sync + fused att2 logit partials --------
#define MM_BM 128
#define MM_BN 128
#define MM_BK 32
#define MM_LDS 40      // row stride in halves (32 + 8 pad)
__global__ void __launch_bounds__(256) k_gemm2(const float* __restrict__ as,
                                               const float* __restrict__ adv) {
    __shared__ __align__(16) __half As[MM_BM][MM_LDS];
    __shared__ __align__(16) __half Bs[MM_BN][MM_LDS];
    int tid = threadIdx.x, lane = tid & 31, w = tid >> 5;
    int wm = w >> 2, wn = w & 3;
    int row0 = blockIdx.x * MM_BM;
    int col0 = blockIdx.y * MM_BN;

    float acc[4][4][4];
#pragma unroll
    for (int i = 0; i < 4; i++)
#pragma unroll
        for (int j = 0; j < 4; j++)
#pragma unroll
            for (int q = 0; q < 4; q++) acc[i][j][q] = 0.f;

    int rA0 = (tid + 0)   >> 2, qA0 = (tid + 0)   & 3;
    int rA1 = (tid + 256) >> 2, qA1 = (tid + 256) & 3;

    uint4 pa0, pa1, pb0, pb1;
    {
        pa0 = make_uint4(0, 0, 0, 0); pa1 = make_uint4(0, 0, 0, 0);
        if (row0 + rA0 < NN)
            pa0 = *reinterpret_cast<const uint4*>(&g_x1h[(size_t)(row0 + rA0) * D1 + qA0 * 8]);
        if (row0 + rA1 < NN)
            pa1 = *reinterpret_cast<const uint4*>(&g_x1h[(size_t)(row0 + rA1) * D1 + qA1 * 8]);
        pb0 = *reinterpret_cast<const uint4*>(&g_w2h[(size_t)(col0 + rA0) * D1 + qA0 * 8]);
        pb1 = *reinterpret_cast<const uint4*>(&g_w2h[(size_t)(col0 + rA1) * D1 + qA1 * 8]);
    }

    for (int kc = 0; kc < D1; kc += MM_BK) {
        *reinterpret_cast<uint4*>(&As[rA0][qA0 * 8]) = pa0;
        *reinterpret_cast<uint4*>(&As[rA1][qA1 * 8]) = pa1;
        *reinterpret_cast<uint4*>(&Bs[rA0][qA0 * 8]) = pb0;
        *reinterpret_cast<uint4*>(&Bs[rA1][qA1 * 8]) = pb1;
        __syncthreads();

        if (kc + MM_BK < D1) {
            int kn = kc + MM_BK;
            pa0 = make_uint4(0, 0, 0, 0); pa1 = make_uint4(0, 0, 0, 0);
            if (row0 + rA0 < NN)
                pa0 = *reinterpret_cast<const uint4*>(&g_x1h[(size_t)(row0 + rA0) * D1 + kn + qA0 * 8]);
            if (row0 + rA1 < NN)
                pa1 = *reinterpret_cast<const uint4*>(&g_x1h[(size_t)(row0 + rA1) * D1 + kn + qA1 * 8]);
            pb0 = *reinterpret_cast<const uint4*>(&g_w2h[(size_t)(col0 + rA0) * D1 + kn + qA0 * 8]);
            pb1 = *reinterpret_cast<const uint4*>(&g_w2h[(size_t)(col0 + rA1) * D1 + kn + qA1 * 8]);
        }

#pragma unroll
        for (int kh = 0; kh < 2; kh++) {
            uint32_t af[4][4], bf[4][2];
#pragma unroll
            for (int mt = 0; mt < 4; mt++) {
                int r = wm * 64 + mt * 16 + (lane & 15);
                int c = kh * 16 + (lane >> 4) * 8;
                uint32_t a = smem_u32(&As[r][c]);
                asm volatile("ldmatrix.sync.aligned.m8n8.x4.shared.b16 {%0,%1,%2,%3}, [%4];"
                    : "=r"(af[mt][0]), "=r"(af[mt][1]), "=r"(af[mt][2]), "=r"(af[mt][3]) : "r"(a));
            }
#pragma unroll
            for (int nt = 0; nt < 4; nt++) {
                int r = wn * 32 + nt * 8 + (lane & 7);
                int c = kh * 16 + ((lane >> 3) & 1) * 8;
                uint32_t a = smem_u32(&Bs[r][c]);
                asm volatile("ldmatrix.sync.aligned.m8n8.x2.shared.b16 {%0,%1}, [%2];"
                    : "=r"(bf[nt][0]), "=r"(bf[nt][1]) : "r"(a));
            }
#pragma unroll
            for (int mt = 0; mt < 4; mt++)
#pragma unroll
                for (int nt = 0; nt < 4; nt++)
                    asm volatile(
                        "mma.sync.aligned.m16n8k16.row.col.f32.f16.f16.f32 "
                        "{%0,%1,%2,%3},{%4,%5,%6,%7},{%8,%9},{%0,%1,%2,%3};"
                        : "+f"(acc[mt][nt][0]), "+f"(acc[mt][nt][1]),
                          "+f"(acc[mt][nt][2]), "+f"(acc[mt][nt][3])
                        : "r"(af[mt][0]), "r"(af[mt][1]), "r"(af[mt][2]), "r"(af[mt][3]),
                          "r"(bf[nt][0]), "r"(bf[nt][1]));
        }
        __syncthreads();
    }

#pragma unroll
    for (int mt = 0; mt < 4; mt++) {
        int rr = row0 + wm * 64 + mt * 16 + (lane >> 2);
#pragma unroll
        for (int nt = 0; nt < 4; nt++) {
            int cc = col0 + wn * 32 + nt * 8 + 2 * (lane & 3);
            if (rr < NN)
                *reinterpret_cast<float2*>(&g_h2[(size_t)rr * HHID + cc]) =
                    make_float2(acc[mt][nt][0], acc[mt][nt][1]);
            if (rr + 8 < NN)
                *reinterpret_cast<float2*>(&g_h2[(size_t)(rr + 8) * HHID + cc]) =
                    make_float2(acc[mt][nt][2], acc[mt][nt][3]);
        }
    }

    // fused attention-logit partials (single head)
    float2 av[4], dv[4];
#pragma unroll
    for (int nt = 0; nt < 4; nt++) {
        int cc = col0 + wn * 32 + nt * 8 + 2 * (lane & 3);
        av[nt] = *reinterpret_cast<const float2*>(&as[cc & (HHID - 1)]);
        dv[nt] = *reinterpret_cast<const float2*>(&adv[cc & (HHID - 1)]);
    }
#pragma unroll
    for (int mt = 0; mt < 4; mt++) {
        int r0 = row0 + wm * 64 + mt * 16 + (lane >> 2);
        float ps0 = 0.f, pd0 = 0.f, ps1 = 0.f, pd1 = 0.f;
#pragma unroll
        for (int nt = 0; nt < 4; nt++) {
            ps0 += acc[mt][nt][0] * av[nt].x + acc[mt][nt][1] * av[nt].y;
            pd0 += acc[mt][nt][0] * dv[nt].x + acc[mt][nt][1] * dv[nt].y;
            ps1 += acc[mt][nt][2] * av[nt].x + acc[mt][nt][3] * av[nt].y;
            pd1 += acc[mt][nt][2] * dv[nt].x + acc[mt][nt][3] * dv[nt].y;
        }
#pragma unroll
        for (int o = 1; o <= 2; o <<= 1) {
            ps0 += __shfl_xor_sync(0xffffffffu, ps0, o);
            pd0 += __shfl_xor_sync(0xffffffffu, pd0, o);
            ps1 += __shfl_xor_sync(0xffffffffu, ps1, o);
            pd1 += __shfl_xor_sync(0xffffffffu, pd1, o);
        }
        if ((lane & 3) == 0) {
            if (r0 < NN) {
                atomicAdd(&g_as2[r0], ps0);
                atomicAdd(&g_ad2[r0], pd0);
            }
            if (r0 + 8 < NN) {
                atomicAdd(&g_as2[r0 + 8], ps1);
                atomicAdd(&g_ad2[r0 + 8], pd1);
            }
        }
    }
}

// ---------------- self-loop ex + den init, layer 2 ----------------------
__global__ void k_self2() {
    int i = blockIdx.x * blockDim.x + threadIdx.x;
    if (i >= NN) return;
    float e = g_as2[i] + g_ad2[i];
    e = e > 0.f ? e : 0.2f * e;
    float ex = expf(e);
    g_exself2[i] = ex;
    g_den2[i] = ex;
}

// ---------------- edge kernel layer 2 ----------------------------------
__global__ void k_edge2(const int* __restrict__ ei) {
    int i = blockIdx.x * blockDim.x + threadIdx.x;
    if (i >= EE) return;
    int s = ei[i], d = ei[EE + i];
    float e = g_as2[s] + g_ad2[d];
    e = e > 0.f ? e : 0.2f * e;
    float ex = expf(e);
    g_ex2s[g_pos[i]] = ex;
    atomicAdd(&g_den2[d], ex);
}

// ---------------- layer-2 aggregation + ReLU + mean pool ---------------
__global__ void k_agg2(const float* __restrict__ b2) {
    int d = blockIdx.x, tid = threadIdx.x;
    int beg = g_offs[d], cnt = g_offs[d + 1] - beg;
    float acc = g_exself2[d] * g_h2[(size_t)d * HHID + tid];
#pragma unroll 4
    for (int i = 0; i < cnt; i++) {
        int s = g_srcs[beg + i];
        acc += g_ex2s[beg + i] * g_h2[(size_t)s * HHID + tid];
    }
    float inv = 1.f / (g_den2[d] + 1e-16f);
    float v = acc * inv + b2[tid];
    v = v > 0.f ? v : 0.f;
    atomicAdd(&g_pooled[tid], v * (1.0f / NN));
}

// ---------------- final MLP ----------------
__global__ void k_final(const float* __restrict__ Wv1, const float* __restrict__ bv1,
                        const float* __restrict__ Wv2, const float* __restrict__ bv2,
                        float* __restrict__ out) {
    __shared__ float sp[HHID];
    __shared__ float wred[4];
    int t = threadIdx.x;   // 128 threads
    for (int c = t; c < HHID; c += 128) sp[c] = g_pooled[c];
    __syncthreads();
    float a = 0.f;
    for (int k = 0; k < HHID; k++) a += sp[k] * Wv1[k * 128 + t];
    a += bv1[t];
    float g = a * normcdff(a);
    float v = g * Wv2[t];
    int lane = t & 31, wid = t >> 5;
#pragma unroll
    for (int o = 16; o; o >>= 1) v += __shfl_xor_sync(0xffffffffu, v, o);
    if (lane == 0) wred[wid] = v;
    __syncthreads();
    if (t == 0) out[0] = wred[0] + wred[1] + wred[2] + wred[3] + bv2[0];
}

// ---------------- launch ----------------
extern "C" void kernel_launch(void* const* d_in, const int* in_sizes, int n_in,
                              void* d_out, int out_size) {
    const float* x       = (const float*)d_in[0];
    const int*   ei      = (const int*)  d_in[1];
    // d_in[2] edge_attr unused (GATConv built without edge_dim)
    const float* W1      = (const float*)d_in[3];
    const float* att_s1  = (const float*)d_in[4];
    const float* att_d1  = (const float*)d_in[5];
    const float* b1      = (const float*)d_in[6];
    const float* W2      = (const float*)d_in[7];
    const float* att_s2  = (const float*)d_in[8];
    const float* att_d2  = (const float*)d_in[9];
    const float* b2      = (const float*)d_in[10];
    const float* Wv1     = (const float*)d_in[11];
    const float* bv1     = (const float*)d_in[12];
    const float* Wv2     = (const float*)d_in[13];
    const float* bv2     = (const float*)d_in[14];
    float* out = (float*)d_out;

    k_zero<<<(NN * 4 + 255) / 256, 256>>>();
    k_hist<<<(EE + 255) / 256, 256>>>(ei);
    k_scan<<<1, 1024>>>();
    k_scatter<<<(EE + 255) / 256, 256>>>(ei);

    k_prepW1<<<(KP * D1 + 255) / 256, 256>>>(W1);
    dim3 gw(D1 / 32, HHID / 32);
    k_prepW2<<<gw, 256>>>(W2);

    dim3 g1((NN + 127) / 128, D1 / 128);
    k_gemm1<<<g1, 256>>>(x, att_s1, att_d1);
    k_self1<<<(NN * 4 + 255) / 256, 256>>>();
    k_edge1<<<(EE + 255) / 256, 256>>>(ei);
    k_agg1<<<NN, 256>>>(b1);

    dim3 g2((NN + MM_BM - 1) / MM_BM, HHID / MM_BN);
    k_gemm2<<<g2, 256>>>(att_s2, att_d2);
    k_self2<<<(NN + 255) / 256, 256>>>();
    k_edge2<<<(EE + 255) / 256, 256>>>(ei);
    k_agg2<<<NN, 256>>>(b2);

    k_final<<<1, 128>>>(Wv1, bv1, Wv2, bv2, out);
}

// round 17
// speedup vs baseline: 1.1687x; 1.1687x over previous
#include <cuda_runtime.h>
#include <cuda_fp16.h>
#include <math.h>
#include <stdint.h>

#define NN 10000
#define EE 160000
#define FIN 70
#define KP 80            // FIN padded to multiple of 16
#define HHID 256
#define D1 1024          // HEADS*HID

typedef unsigned long long u64;

__device__ __forceinline__ uint32_t smem_u32(const void* p) {
    uint32_t a;
    asm("{ .reg .u64 t; cvta.to.shared.u64 t, %1; cvt.u32.u64 %0, t; }" : "=r"(a) : "l"(p));
    return a;
}
__device__ __forceinline__ float4 h4_to_f4(u64 v) {
    __half2 lo = reinterpret_cast<__half2*>(&v)[0];
    __half2 hi = reinterpret_cast<__half2*>(&v)[1];
    float2 a = __half22float2(lo), b = __half22float2(hi);
    return make_float4(a.x, a.y, b.x, b.y);
}

// ---------------- device scratch (no allocations allowed) ----------------
__device__ __align__(16) __half g_h1h[NN * D1];   // layer-1 linear out (fp16)
__device__ __align__(16) __half g_x1h[NN * D1];   // relu(agg1+b1) fp16 (GEMM2 A)
__device__ __align__(16) __half g_w1h[D1 * KP];   // W1^T fp16 [n][k], k padded to 80
__device__ __align__(16) __half g_w2h[HHID * D1]; // W2^T fp16 [n][k]
__device__ __align__(16) float g_as1[NN * 4];
__device__ __align__(16) float g_ad1[NN * 4];
__device__ __align__(16) __half g_h2h[NN * HHID]; // layer-2 linear out (fp16)
__device__ float g_as2[NN];
__device__ float g_ad2[NN];
__device__ __align__(16) float g_ex1s[EE * 4];    // exp(leaky) per edge, DST-SORTED
__device__ float g_ex2s[EE];
__device__ __align__(16) float g_den1[NN * 4];    // edge-only denom (self added in agg)
__device__ float g_den2[NN];
__device__ float g_pooled[HHID];
__device__ int   g_deg[NN];
__device__ int   g_offs[NN + 1];
__device__ int   g_cursor[NN];
__device__ int   g_srcs[EE];
__device__ int   g_pos[EE];      // original edge -> sorted slot

// ---------------- small utils ----------------
__global__ void k_zero() {
    int i = blockIdx.x * blockDim.x + threadIdx.x;
    if (i < NN * 4) { g_as1[i] = 0.f; g_ad1[i] = 0.f; g_den1[i] = 0.f; }
    if (i < NN) { g_deg[i] = 0; g_as2[i] = 0.f; g_ad2[i] = 0.f; g_den2[i] = 0.f; }
    if (i < HHID) g_pooled[i] = 0.f;
}

__global__ void k_hist(const int* __restrict__ ei) {
    int i = blockIdx.x * blockDim.x + threadIdx.x;
    if (i < EE) atomicAdd(&g_deg[ei[EE + i]], 1);
}

__global__ void k_scan() {
    __shared__ int sbuf[1024];
    int t = threadIdx.x;
    int base = t * 10;
    int loc[10];
    int sum = 0;
#pragma unroll
    for (int q = 0; q < 10; q++) {
        int idx = base + q;
        int v = (idx < NN) ? g_deg[idx] : 0;
        loc[q] = sum; sum += v;
    }
    sbuf[t] = sum;
    __syncthreads();
    for (int off = 1; off < 1024; off <<= 1) {
        int tmp = (t >= off) ? sbuf[t - off] : 0;
        __syncthreads();
        sbuf[t] += tmp;
        __syncthreads();
    }
    int excl = sbuf[t] - sum;
#pragma unroll
    for (int q = 0; q < 10; q++) {
        int idx = base + q;
        if (idx < NN) { int o = excl + loc[q]; g_offs[idx] = o; g_cursor[idx] = o; }
    }
    if (t == 1023) g_offs[NN] = sbuf[1023];
}

__global__ void k_scatter(const int* __restrict__ ei) {
    int i = blockIdx.x * blockDim.x + threadIdx.x;
    if (i < EE) {
        int dnode = ei[EE + i];
        int pos = atomicAdd(&g_cursor[dnode], 1);
        g_srcs[pos] = ei[i];
        g_pos[i] = pos;
    }
}

// ---------------- W1 [70,1024] fp32 -> g_w1h [1024][80] fp16 ------------
__global__ void k_prepW1(const float* __restrict__ W1) {
    int id = blockIdx.x * blockDim.x + threadIdx.x;  // k-major over [KP][D1]
    if (id >= KP * D1) return;
    int k = id >> 10, n = id & 1023;
    float v = (k < FIN) ? W1[k * D1 + n] : 0.f;
    g_w1h[(size_t)n * KP + k] = __float2half(v);
}

// ---------------- W2 [1024,256] fp32 -> g_w2h [256][1024] fp16 ----------
__global__ void k_prepW2(const float* __restrict__ W2) {
    __shared__ float t[32][33];
    int k0 = blockIdx.x * 32, n0 = blockIdx.y * 32;
    int tx = threadIdx.x & 31, ty = threadIdx.x >> 5;   // 256 threads
#pragma unroll
    for (int i = 0; i < 4; i++)
        t[ty + 8 * i][tx] = W2[(k0 + ty + 8 * i) * HHID + n0 + tx];
    __syncthreads();
#pragma unroll
    for (int i = 0; i < 4; i++)
        g_w2h[(size_t)(n0 + ty + 8 * i) * D1 + k0 + tx] = __float2half(t[tx][ty + 8 * i]);
}

// ---------------- GEMM1 via HMMA + fused att1 logit partials ------------
#define G1_LDS 88
__global__ void __launch_bounds__(256) k_gemm1(const float* __restrict__ x,
                                               const float* __restrict__ as,
                                               const float* __restrict__ adv) {
    __shared__ __align__(16) __half As[128][G1_LDS];
    __shared__ __align__(16) __half Bs[128][G1_LDS];
    int tid = threadIdx.x, lane = tid & 31, w = tid >> 5;
    int wm = w >> 2, wn = w & 3;
    int row0 = blockIdx.x * 128;
    int col0 = blockIdx.y * 128;

    for (int idx = tid; idx < 128 * KP; idx += 256) {
        int r = idx / KP, c = idx - r * KP;
        float v = 0.f;
        if (c < FIN && row0 + r < NN) v = x[(size_t)(row0 + r) * FIN + c];
        As[r][c] = __float2half(v);
    }
    for (int idx = tid; idx < 128 * 10; idx += 256) {
        int r = idx / 10, q = idx - r * 10;
        *reinterpret_cast<uint4*>(&Bs[r][q * 8]) =
            *reinterpret_cast<const uint4*>(&g_w1h[(size_t)(col0 + r) * KP + q * 8]);
    }
    __syncthreads();

    float acc[4][4][4];
#pragma unroll
    for (int i = 0; i < 4; i++)
#pragma unroll
        for (int j = 0; j < 4; j++)
#pragma unroll
            for (int q = 0; q < 4; q++) acc[i][j][q] = 0.f;

#pragma unroll
    for (int kh = 0; kh < 5; kh++) {
        uint32_t af[4][4], bf[4][2];
#pragma unroll
        for (int mt = 0; mt < 4; mt++) {
            int r = wm * 64 + mt * 16 + (lane & 15);
            int c = kh * 16 + (lane >> 4) * 8;
            uint32_t a = smem_u32(&As[r][c]);
            asm volatile("ldmatrix.sync.aligned.m8n8.x4.shared.b16 {%0,%1,%2,%3}, [%4];"
                : "=r"(af[mt][0]), "=r"(af[mt][1]), "=r"(af[mt][2]), "=r"(af[mt][3]) : "r"(a));
        }
#pragma unroll
        for (int nt = 0; nt < 4; nt++) {
            int r = wn * 32 + nt * 8 + (lane & 7);
            int c = kh * 16 + ((lane >> 3) & 1) * 8;
            uint32_t a = smem_u32(&Bs[r][c]);
            asm volatile("ldmatrix.sync.aligned.m8n8.x2.shared.b16 {%0,%1}, [%2];"
                : "=r"(bf[nt][0]), "=r"(bf[nt][1]) : "r"(a));
        }
#pragma unroll
        for (int mt = 0; mt < 4; mt++)
#pragma unroll
            for (int nt = 0; nt < 4; nt++)
                asm volatile(
                    "mma.sync.aligned.m16n8k16.row.col.f32.f16.f16.f32 "
                    "{%0,%1,%2,%3},{%4,%5,%6,%7},{%8,%9},{%0,%1,%2,%3};"
                    : "+f"(acc[mt][nt][0]), "+f"(acc[mt][nt][1]),
                      "+f"(acc[mt][nt][2]), "+f"(acc[mt][nt][3])
                    : "r"(af[mt][0]), "r"(af[mt][1]), "r"(af[mt][2]), "r"(af[mt][3]),
                      "r"(bf[nt][0]), "r"(bf[nt][1]));
    }

    // store h1 (fp16)
#pragma unroll
    for (int mt = 0; mt < 4; mt++) {
        int rr = row0 + wm * 64 + mt * 16 + (lane >> 2);
#pragma unroll
        for (int nt = 0; nt < 4; nt++) {
            int cc = col0 + wn * 32 + nt * 8 + 2 * (lane & 3);
            if (rr < NN)
                *reinterpret_cast<__half2*>(&g_h1h[(size_t)rr * D1 + cc]) =
                    __floats2half2_rn(acc[mt][nt][0], acc[mt][nt][1]);
            if (rr + 8 < NN)
                *reinterpret_cast<__half2*>(&g_h1h[(size_t)(rr + 8) * D1 + cc]) =
                    __floats2half2_rn(acc[mt][nt][2], acc[mt][nt][3]);
        }
    }

    // fused attention-logit partials (fp32 acc): head hd = col0>>8
    int hd = col0 >> 8;
    float2 av[4], dv[4];
#pragma unroll
    for (int nt = 0; nt < 4; nt++) {
        int cc = col0 + wn * 32 + nt * 8 + 2 * (lane & 3);
        av[nt] = *reinterpret_cast<const float2*>(&as[cc]);
        dv[nt] = *reinterpret_cast<const float2*>(&adv[cc]);
    }
#pragma unroll
    for (int mt = 0; mt < 4; mt++) {
        int r0 = row0 + wm * 64 + mt * 16 + (lane >> 2);
        float ps0 = 0.f, pd0 = 0.f, ps1 = 0.f, pd1 = 0.f;
#pragma unroll
        for (int nt = 0; nt < 4; nt++) {
            ps0 += acc[mt][nt][0] * av[nt].x + acc[mt][nt][1] * av[nt].y;
            pd0 += acc[mt][nt][0] * dv[nt].x + acc[mt][nt][1] * dv[nt].y;
            ps1 += acc[mt][nt][2] * av[nt].x + acc[mt][nt][3] * av[nt].y;
            pd1 += acc[mt][nt][2] * dv[nt].x + acc[mt][nt][3] * dv[nt].y;
        }
#pragma unroll
        for (int o = 1; o <= 2; o <<= 1) {
            ps0 += __shfl_xor_sync(0xffffffffu, ps0, o);
            pd0 += __shfl_xor_sync(0xffffffffu, pd0, o);
            ps1 += __shfl_xor_sync(0xffffffffu, ps1, o);
            pd1 += __shfl_xor_sync(0xffffffffu, pd1, o);
        }
        if ((lane & 3) == 0) {
            if (r0 < NN) {
                atomicAdd(&g_as1[r0 * 4 + hd], ps0);
                atomicAdd(&g_ad1[r0 * 4 + hd], pd0);
            }
            if (r0 + 8 < NN) {
                atomicAdd(&g_as1[(r0 + 8) * 4 + hd], ps1);
                atomicAdd(&g_ad1[(r0 + 8) * 4 + hd], pd1);
            }
        }
    }
}

// ---------------- edge kernel layer 1: ex (sorted) + denom atomics -----
__global__ void k_edge1(const int* __restrict__ ei) {
    int i = blockIdx.x * blockDim.x + threadIdx.x;
    if (i >= EE) return;
    int s = ei[i], d = ei[EE + i];
    float4 a = *reinterpret_cast<const float4*>(&g_as1[s * 4]);
    float4 b = *reinterpret_cast<const float4*>(&g_ad1[d * 4]);
    float e0 = a.x + b.x; e0 = e0 > 0.f ? e0 : 0.2f * e0; e0 = expf(e0);
    float e1 = a.y + b.y; e1 = e1 > 0.f ? e1 : 0.2f * e1; e1 = expf(e1);
    float e2 = a.z + b.z; e2 = e2 > 0.f ? e2 : 0.2f * e2; e2 = expf(e2);
    float e3 = a.w + b.w; e3 = e3 > 0.f ? e3 : 0.2f * e3; e3 = expf(e3);
    int pos = g_pos[i];
    *reinterpret_cast<float4*>(&g_ex1s[(size_t)pos * 4]) = make_float4(e0, e1, e2, e3);
    atomicAdd(&g_den1[d * 4 + 0], e0);
    atomicAdd(&g_den1[d * 4 + 1], e1);
    atomicAdd(&g_den1[d * 4 + 2], e2);
    atomicAdd(&g_den1[d * 4 + 3], e3);
}

// ---------------- layer-1 aggregation: single pass, vectorized ---------
// thread t handles channels [4t, 4t+4) -> one head per thread (h = t>>6)
// self-loop ex computed locally; den1 holds edge-only sum.
__global__ void k_agg1(const float* __restrict__ b1) {
    int d = blockIdx.x, t = threadIdx.x;
    int beg = g_offs[d], cnt = g_offs[d + 1] - beg;
    int h = t >> 6;
    const u64* hb = reinterpret_cast<const u64*>(g_h1h);

    // self-loop term (computed from logits, not stored)
    float eself = g_as1[d * 4 + h] + g_ad1[d * 4 + h];
    eself = eself > 0.f ? eself : 0.2f * eself;
    float ex = expf(eself);
    float4 f = h4_to_f4(hb[(size_t)d * 256 + t]);
    float ax = ex * f.x, ay = ex * f.y, az = ex * f.z, aw = ex * f.w;

#pragma unroll 4
    for (int i = 0; i < cnt; i++) {
        int s = g_srcs[beg + i];
        float e = g_ex1s[(size_t)(beg + i) * 4 + h];
        float4 g = h4_to_f4(hb[(size_t)s * 256 + t]);
        ax += e * g.x; ay += e * g.y; az += e * g.z; aw += e * g.w;
    }

    float inv = 1.f / (g_den1[d * 4 + h] + ex + 1e-16f);
    float4 bb = *reinterpret_cast<const float4*>(&b1[4 * t]);
    __half2 lo = __floats2half2_rn(fmaxf(ax * inv + bb.x, 0.f),
                                   fmaxf(ay * inv + bb.y, 0.f));
    __half2 hi = __floats2half2_rn(fmaxf(az * inv + bb.z, 0.f),
                                   fmaxf(aw * inv + bb.w, 0.f));
    u64 outv;
    reinterpret_cast<__half2*>(&outv)[0] = lo;
    reinterpret_cast<__half2*>(&outv)[1] = hi;
    *reinterpret_cast<u64*>(&g_x1h[(size_t)d * D1 + 4 * t]) = outv;
}

// ---------------- GEMM2 via mma.sync + fused att2 logit partials --------
#define MM_BM 128
#define MM_BN 128
#define MM_BK 32
#define MM_LDS 40      // row stride in halves (32 + 8 pad)
__global__ void __launch_bounds__(256) k_gemm2(const float* __restrict__ as,
                                               const float* __restrict__ adv) {
    __shared__ __align__(16) __half As[MM_BM][MM_LDS];
    __shared__ __align__(16) __half Bs[MM_BN][MM_LDS];
    int tid = threadIdx.x, lane = tid & 31, w = tid >> 5;
    int wm = w >> 2, wn = w & 3;
    int row0 = blockIdx.x * MM_BM;
    int col0 = blockIdx.y * MM_BN;

    float acc[4][4][4];
#pragma unroll
    for (int i = 0; i < 4; i++)
#pragma unroll
        for (int j = 0; j < 4; j++)
#pragma unroll
            for (int q = 0; q < 4; q++) acc[i][j][q] = 0.f;

    int rA0 = (tid + 0)   >> 2, qA0 = (tid + 0)   & 3;
    int rA1 = (tid + 256) >> 2, qA1 = (tid + 256) & 3;

    uint4 pa0, pa1, pb0, pb1;
    {
        pa0 = make_uint4(0, 0, 0, 0); pa1 = make_uint4(0, 0, 0, 0);
        if (row0 + rA0 < NN)
            pa0 = *reinterpret_cast<const uint4*>(&g_x1h[(size_t)(row0 + rA0) * D1 + qA0 * 8]);
        if (row0 + rA1 < NN)
            pa1 = *reinterpret_cast<const uint4*>(&g_x1h[(size_t)(row0 + rA1) * D1 + qA1 * 8]);
        pb0 = *reinterpret_cast<const uint4*>(&g_w2h[(size_t)(col0 + rA0) * D1 + qA0 * 8]);
        pb1 = *reinterpret_cast<const uint4*>(&g_w2h[(size_t)(col0 + rA1) * D1 + qA1 * 8]);
    }

    for (int kc = 0; kc < D1; kc += MM_BK) {
        *reinterpret_cast<uint4*>(&As[rA0][qA0 * 8]) = pa0;
        *reinterpret_cast<uint4*>(&As[rA1][qA1 * 8]) = pa1;
        *reinterpret_cast<uint4*>(&Bs[rA0][qA0 * 8]) = pb0;
        *reinterpret_cast<uint4*>(&Bs[rA1][qA1 * 8]) = pb1;
        __syncthreads();

        if (kc + MM_BK < D1) {
            int kn = kc + MM_BK;
            pa0 = make_uint4(0, 0, 0, 0); pa1 = make_uint4(0, 0, 0, 0);
            if (row0 + rA0 < NN)
                pa0 = *reinterpret_cast<const uint4*>(&g_x1h[(size_t)(row0 + rA0) * D1 + kn + qA0 * 8]);
            if (row0 + rA1 < NN)
                pa1 = *reinterpret_cast<const uint4*>(&g_x1h[(size_t)(row0 + rA1) * D1 + kn + qA1 * 8]);
            pb0 = *reinterpret_cast<const uint4*>(&g_w2h[(size_t)(col0 + rA0) * D1 + kn + qA0 * 8]);
            pb1 = *reinterpret_cast<const uint4*>(&g_w2h[(size_t)(col0 + rA1) * D1 + kn + qA1 * 8]);
        }

#pragma unroll
        for (int kh = 0; kh < 2; kh++) {
            uint32_t af[4][4], bf[4][2];
#pragma unroll
            for (int mt = 0; mt < 4; mt++) {
                int r = wm * 64 + mt * 16 + (lane & 15);
                int c = kh * 16 + (lane >> 4) * 8;
                uint32_t a = smem_u32(&As[r][c]);
                asm volatile("ldmatrix.sync.aligned.m8n8.x4.shared.b16 {%0,%1,%2,%3}, [%4];"
                    : "=r"(af[mt][0]), "=r"(af[mt][1]), "=r"(af[mt][2]), "=r"(af[mt][3]) : "r"(a));
            }
#pragma unroll
            for (int nt = 0; nt < 4; nt++) {
                int r = wn * 32 + nt * 8 + (lane & 7);
                int c = kh * 16 + ((lane >> 3) & 1) * 8;
                uint32_t a = smem_u32(&Bs[r][c]);
                asm volatile("ldmatrix.sync.aligned.m8n8.x2.shared.b16 {%0,%1}, [%2];"
                    : "=r"(bf[nt][0]), "=r"(bf[nt][1]) : "r"(a));
            }
#pragma unroll
            for (int mt = 0; mt < 4; mt++)
#pragma unroll
                for (int nt = 0; nt < 4; nt++)
                    asm volatile(
                        "mma.sync.aligned.m16n8k16.row.col.f32.f16.f16.f32 "
                        "{%0,%1,%2,%3},{%4,%5,%6,%7},{%8,%9},{%0,%1,%2,%3};"
                        : "+f"(acc[mt][nt][0]), "+f"(acc[mt][nt][1]),
                          "+f"(acc[mt][nt][2]), "+f"(acc[mt][nt][3])
                        : "r"(af[mt][0]), "r"(af[mt][1]), "r"(af[mt][2]), "r"(af[mt][3]),
                          "r"(bf[nt][0]), "r"(bf[nt][1]));
        }
        __syncthreads();
    }

    // store h2 (fp16)
#pragma unroll
    for (int mt = 0; mt < 4; mt++) {
        int rr = row0 + wm * 64 + mt * 16 + (lane >> 2);
#pragma unroll
        for (int nt = 0; nt < 4; nt++) {
            int cc = col0 + wn * 32 + nt * 8 + 2 * (lane & 3);
            if (rr < NN)
                *reinterpret_cast<__half2*>(&g_h2h[(size_t)rr * HHID + cc]) =
                    __floats2half2_rn(acc[mt][nt][0], acc[mt][nt][1]);
            if (rr + 8 < NN)
                *reinterpret_cast<__half2*>(&g_h2h[(size_t)(rr + 8) * HHID + cc]) =
                    __floats2half2_rn(acc[mt][nt][2], acc[mt][nt][3]);
        }
    }

    // fused attention-logit partials (single head)
    float2 av[4], dv[4];
#pragma unroll
    for (int nt = 0; nt < 4; nt++) {
        int cc = col0 + wn * 32 + nt * 8 + 2 * (lane & 3);
        av[nt] = *reinterpret_cast<const float2*>(&as[cc & (HHID - 1)]);
        dv[nt] = *reinterpret_cast<const float2*>(&adv[cc & (HHID - 1)]);
    }
#pragma unroll
    for (int mt = 0; mt < 4; mt++) {
        int r0 = row0 + wm * 64 + mt * 16 + (lane >> 2);
        float ps0 = 0.f, pd0 = 0.f, ps1 = 0.f, pd1 = 0.f;
#pragma unroll
        for (int nt = 0; nt < 4; nt++) {
            ps0 += acc[mt][nt][0] * av[nt].x + acc[mt][nt][1] * av[nt].y;
            pd0 += acc[mt][nt][0] * dv[nt].x + acc[mt][nt][1] * dv[nt].y;
            ps1 += acc[mt][nt][2] * av[nt].x + acc[mt][nt][3] * av[nt].y;
            pd1 += acc[mt][nt][2] * dv[nt].x + acc[mt][nt][3] * dv[nt].y;
        }
#pragma unroll
        for (int o = 1; o <= 2; o <<= 1) {
            ps0 += __shfl_xor_sync(0xffffffffu, ps0, o);
            pd0 += __shfl_xor_sync(0xffffffffu, pd0, o);
            ps1 += __shfl_xor_sync(0xffffffffu, ps1, o);
            pd1 += __shfl_xor_sync(0xffffffffu, pd1, o);
        }
        if ((lane & 3) == 0) {
            if (r0 < NN) {
                atomicAdd(&g_as2[r0], ps0);
                atomicAdd(&g_ad2[r0], pd0);
            }
            if (r0 + 8 < NN) {
                atomicAdd(&g_as2[r0 + 8], ps1);
                atomicAdd(&g_ad2[r0 + 8], pd1);
            }
        }
    }
}

// ---------------- edge kernel layer 2 ----------------------------------
__global__ void k_edge2(const int* __restrict__ ei) {
    int i = blockIdx.x * blockDim.x + threadIdx.x;
    if (i >= EE) return;
    int s = ei[i], d = ei[EE + i];
    float e = g_as2[s] + g_ad2[d];
    e = e > 0.f ? e : 0.2f * e;
    float ex = expf(e);
    g_ex2s[g_pos[i]] = ex;
    atomicAdd(&g_den2[d], ex);
}

// ---------------- layer-2 aggregation + ReLU + mean pool (fp16 h2) -----
__global__ void k_agg2(const float* __restrict__ b2) {
    int d = blockIdx.x, tid = threadIdx.x;
    int beg = g_offs[d], cnt = g_offs[d + 1] - beg;

    // self-loop ex computed locally
    float eself = g_as2[d] + g_ad2[d];
    eself = eself > 0.f ? eself : 0.2f * eself;
    float ex = expf(eself);

    float acc = ex * __half2float(g_h2h[(size_t)d * HHID + tid]);
#pragma unroll 4
    for (int i = 0; i < cnt; i++) {
        int s = g_srcs[beg + i];
        acc += g_ex2s[beg + i] * __half2float(g_h2h[(size_t)s * HHID + tid]);
    }
    float inv = 1.f / (g_den2[d] + ex + 1e-16f);
    float v = acc * inv + b2[tid];
    v = v > 0.f ? v : 0.f;
    atomicAdd(&g_pooled[tid], v * (1.0f / NN));
}

// ---------------- final MLP ----------------
__global__ void k_final(const float* __restrict__ Wv1, const float* __restrict__ bv1,
                        const float* __restrict__ Wv2, const float* __restrict__ bv2,
                        float* __restrict__ out) {
    __shared__ float sp[HHID];
    __shared__ float wred[4];
    int t = threadIdx.x;   // 128 threads
    for (int c = t; c < HHID; c += 128) sp[c] = g_pooled[c];
    __syncthreads();
    float a = 0.f;
    for (int k = 0; k < HHID; k++) a += sp[k] * Wv1[k * 128 + t];
    a += bv1[t];
    float g = a * normcdff(a);
    float v = g * Wv2[t];
    int lane = t & 31, wid = t >> 5;
#pragma unroll
    for (int o = 16; o; o >>= 1) v += __shfl_xor_sync(0xffffffffu, v, o);
    if (lane == 0) wred[wid] = v;
    __syncthreads();
    if (t == 0) out[0] = wred[0] + wred[1] + wred[2] + wred[3] + bv2[0];
}

// ---------------- launch ----------------
extern "C" void kernel_launch(void* const* d_in, const int* in_sizes, int n_in,
                              void* d_out, int out_size) {
    const float* x       = (const float*)d_in[0];
    const int*   ei      = (const int*)  d_in[1];
    // d_in[2] edge_attr unused (GATConv built without edge_dim)
    const float* W1      = (const float*)d_in[3];
    const float* att_s1  = (const float*)d_in[4];
    const float* att_d1  = (const float*)d_in[5];
    const float* b1      = (const float*)d_in[6];
    const float* W2      = (const float*)d_in[7];
    const float* att_s2  = (const float*)d_in[8];
    const float* att_d2  = (const float*)d_in[9];
    const float* b2      = (const float*)d_in[10];
    const float* Wv1     = (const float*)d_in[11];
    const float* bv1     = (const float*)d_in[12];
    const float* Wv2     = (const float*)d_in[13];
    const float* bv2     = (const float*)d_in[14];
    float* out = (float*)d_out;

    k_zero<<<(NN * 4 + 255) / 256, 256>>>();
    k_hist<<<(EE + 255) / 256, 256>>>(ei);
    k_scan<<<1, 1024>>>();
    k_scatter<<<(EE + 255) / 256, 256>>>(ei);

    k_prepW1<<<(KP * D1 + 255) / 256, 256>>>(W1);
    dim3 gw(D1 / 32, HHID / 32);
    k_prepW2<<<gw, 256>>>(W2);

    dim3 g1((NN + 127) / 128, D1 / 128);
    k_gemm1<<<g1, 256>>>(x, att_s1, att_d1);
    k_edge1<<<(EE + 255) / 256, 256>>>(ei);
    k_agg1<<<NN, 256>>>(b1);

    dim3 g2((NN + MM_BM - 1) / MM_BM, HHID / MM_BN);
    k_gemm2<<<g2, 256>>>(att_s2, att_d2);
    k_edge2<<<(EE + 255) / 256, 256>>>(ei);
    k_agg2<<<NN, 256>>>(b2);

    k_final<<<1, 128>>>(Wv1, bv1, Wv2, bv2, out);
}